// round 11
// baseline (speedup 1.0000x reference)
#include <cuda_runtime.h>
#include <cuda_bf16.h>
#include <cstdint>

#define S_LEN  8192
#define BH     32
#define NWIN   511
#define WTOT   (5*128*256 + 128*128)

#define M1 (BH*NWIN*8)   // 130816
#define M2 (BH*NWIN*4)   // 65408
#define M3 (BH*NWIN*2)   // 32704
#define M4 (BH*NWIN)     // 16352

__device__ __nv_bfloat16 g_w_hi[WTOT];
__device__ __nv_bfloat16 g_w_lo[WTOT];
__device__ float         g_pew[16 * 128];
__device__ __nv_bfloat16 g_a0_hi[(size_t)BH*NWIN*16*128], g_a0_lo[(size_t)BH*NWIN*16*128];
__device__ __nv_bfloat16 g_a1_hi[(size_t)M1*128],         g_a1_lo[(size_t)M1*128];
__device__ __nv_bfloat16 g_a2_hi[(size_t)M2*128],         g_a2_lo[(size_t)M2*128];
__device__ __nv_bfloat16 g_a3_hi[(size_t)M3*128],         g_a3_lo[(size_t)M3*128];

union U4b { __nv_bfloat16 b[4]; unsigned long long u; };
union U2b { __nv_bfloat16 b[2]; uint32_t u; };

// ---------------------------------------------------------------------------
__global__ void split_weights_kernel(const float* __restrict__ wd,
                                     const float* __restrict__ ws) {
    int i = blockIdx.x * blockDim.x + threadIdx.x;
    if (i >= WTOT) return;
    float v = (i < 5*128*256) ? wd[i] : ws[i - 5*128*256];
    __nv_bfloat16 h = __float2bfloat16(v);
    g_w_hi[i] = h;
    g_w_lo[i] = __float2bfloat16(v - __bfloat162float(h));
}

__global__ void prep_pew_kernel(const float* __restrict__ wd,
                                const float* __restrict__ pe) {
    int idx = blockIdx.x * blockDim.x + threadIdx.x;   // 2048
    int j = idx >> 7, n = idx & 127;
    float s = 0.f;
    for (int d = 0; d < 128; ++d) {
        s += pe[(2*j)*128 + d]   * wd[n*256 + d];
        s += pe[(2*j+1)*128 + d] * wd[n*256 + 128 + d];
    }
    g_pew[idx] = s;
}

__global__ void zero_out_kernel(float* __restrict__ out) {
    int i = blockIdx.x * 256 + threadIdx.x;
    if (i < 4096)
        out[(size_t)(i >> 7) * 512 * 128 + (i & 127)] = 0.f;
}

// ---------------------------------------------------------------------------
__device__ __forceinline__ uint32_t u32p(const void* p) {
    return (uint32_t)__cvta_generic_to_shared(p);
}
__device__ __forceinline__ void ldmx4(uint32_t* r, uint32_t addr) {
    asm volatile("ldmatrix.sync.aligned.m8n8.x4.shared.b16 {%0,%1,%2,%3}, [%4];"
                 : "=r"(r[0]), "=r"(r[1]), "=r"(r[2]), "=r"(r[3]) : "r"(addr));
}
__device__ __forceinline__ void mma16816(float* c, const uint32_t* a,
                                         uint32_t b0, uint32_t b1) {
    asm volatile("mma.sync.aligned.m16n8k16.row.col.f32.bf16.bf16.f32 "
                 "{%0,%1,%2,%3}, {%4,%5,%6,%7}, {%8,%9}, {%0,%1,%2,%3};"
                 : "+f"(c[0]), "+f"(c[1]), "+f"(c[2]), "+f"(c[3])
                 : "r"(a[0]), "r"(a[1]), "r"(a[2]), "r"(a[3]), "r"(b0), "r"(b1));
}
__device__ __forceinline__ float silu_f(float x) { return x / (1.f + __expf(-x)); }

__device__ __forceinline__ void cpasync16(uint32_t dst, const void* src) {
    asm volatile("cp.async.cg.shared.global [%0], [%1], 16;" :: "r"(dst), "l"(src));
}
__device__ __forceinline__ void cpasync16z(uint32_t dst, const void* src, bool v) {
    int sz = v ? 16 : 0;
    asm volatile("cp.async.cg.shared.global [%0], [%1], 16, %2;"
                 :: "r"(dst), "l"(src), "r"(sz));
}
__device__ __forceinline__ void cpcommit() {
    asm volatile("cp.async.commit_group;" ::: "memory");
}
__device__ __forceinline__ void cpwait0() { asm volatile("cp.async.wait_group 0;" ::: "memory"); }

__device__ __forceinline__ void silu_split_store(__nv_bfloat16* hiA, __nv_bfloat16* loA,
                                                 size_t idx, float v0, float v1) {
    v0 = silu_f(v0); v1 = silu_f(v1);
    U2b hi, lo;
    hi.b[0] = __float2bfloat16(v0);
    hi.b[1] = __float2bfloat16(v1);
    lo.b[0] = __float2bfloat16(v0 - __bfloat162float(hi.b[0]));
    lo.b[1] = __float2bfloat16(v1 - __bfloat162float(hi.b[1]));
    *(uint32_t*)(hiA + idx) = hi.u;
    *(uint32_t*)(loA + idx) = lo.u;
}

// B chunk [128 n x 64 k] hi+lo -> swizzled smem
__device__ __forceinline__ void prefB(uint32_t bufU,
        const __nv_bfloat16* __restrict__ wh, const __nv_bfloat16* __restrict__ wl,
        int KDIM, int kb, int tid) {
#pragma unroll
    for (int it = 0; it < 8; ++it) {
        int i = tid + it * 256;
        int g = i & 7, n = (i >> 3) & 127, hl = i >> 10;
        const __nv_bfloat16* src = (hl ? wl : wh) + n * KDIM + kb + g * 8;
        uint32_t dst = bufU + hl * 16384 + n * 128 + ((g ^ (n & 7)) << 4);
        cpasync16(dst, src);
    }
}

// A chunk [64 rows x 64 k] hi+lo from pre-split act arrays
__device__ __forceinline__ void prefA64(uint32_t bufU,
        const __nv_bfloat16* __restrict__ aHi, const __nv_bfloat16* __restrict__ aLo,
        int KD, int Mtot, int mt, int kb, int tid) {
#pragma unroll
    for (int it = 0; it < 4; ++it) {
        int i = tid + it * 256;                 // 1024 copies
        int g = i & 7, row = (i >> 3) & 63, hl = i >> 9;
        int mrow = mt * 64 + row;
        bool v = mrow < Mtot;
        const __nv_bfloat16* src = (hl ? aLo : aHi)
                                 + (size_t)(v ? mrow : 0) * KD + kb + g * 8;
        uint32_t dst = bufU + hl * 8192 + row * 128 + ((g ^ (row & 7)) << 4);
        cpasync16z(dst, src, v);
    }
}

// R=1 x T=8 warp tile over one 64-col chunk (8 warps: 4 row x 2 colgroup)
__device__ __forceinline__ void mma_r1t8(
    float (&acc)[8][4],
    uint32_t aHiU, uint32_t aLoU, uint32_t bHiU, uint32_t bLoU,
    int rt, int cg, int lane)
{
    const int a_rowoff = (lane & 7) + (((lane >> 3) & 1) << 3);
    const int a_koff   = (lane >> 4) << 3;
    const int b_nl     = lane & 7;
    const int b_koff   = ((lane >> 3) & 1) << 3;
    const int b_nts    = lane >> 4;
#pragma unroll
    for (int kq = 0; kq < 64; kq += 16) {
        int Rr = rt * 16 + a_rowoff;
        int kc = kq + a_koff;
        int offs = Rr * 128 + (((kc >> 3) ^ (Rr & 7)) << 4);
        uint32_t aH[4], aL[4];
        ldmx4(aH, aHiU + offs);
        ldmx4(aL, aLoU + offs);
#pragma unroll
        for (int tp = 0; tp < 4; tp++) {
            int n = (cg * 8 + tp * 2 + b_nts) * 8 + b_nl;
            int cs = ((kq + b_koff) >> 3) ^ (n & 7);
            uint32_t boff = (uint32_t)(n * 128 + (cs << 4));
            uint32_t bH[4], bL[4];
            ldmx4(bH, bHiU + boff);
            ldmx4(bL, bLoU + boff);
#pragma unroll
            for (int sub = 0; sub < 2; sub++) {
                float* cc = acc[tp * 2 + sub];
                mma16816(cc, aH, bH[2*sub], bH[2*sub+1]);
                mma16816(cc, aL, bH[2*sub], bH[2*sub+1]);
                mma16816(cc, aH, bL[2*sub], bL[2*sub+1]);
            }
        }
    }
}

// ===========================================================================
// G0: 256 threads, M-tile=64 pairs, 2 CTAs/SM.
// smem: A0 @0 (hi 0 / lo 8192), A1 @16384; B0 @32768 (hi/lo 16384), B1 @65536;
//       pew @98304 (8KB).  Total 106496.
// ===========================================================================
#define G0_PEW  98304
#define G0_SMEM (98304 + 8192)

__device__ __forceinline__ void g0_sts_A(char* sm, int bufByte, const float4* rA,
                                         int tid) {
#pragma unroll
    for (int t = 0; t < 4; ++t) {
        int f = tid + t * 256, row = f >> 4, fc = f & 15;
        float v[4] = {rA[t].x, rA[t].y, rA[t].z, rA[t].w};
        U4b hi, lo;
#pragma unroll
        for (int j = 0; j < 4; j++) {
            hi.b[j] = __float2bfloat16(v[j]);
            lo.b[j] = __float2bfloat16(v[j] - __bfloat162float(hi.b[j]));
        }
        int g = fc >> 1;
        int off = bufByte + row * 128 + ((g ^ (row & 7)) << 4) + (fc & 1) * 8;
        *(unsigned long long*)(sm + off)        = hi.u;
        *(unsigned long long*)(sm + off + 8192) = lo.u;
    }
}

__global__ void __launch_bounds__(256, 2)
g0_kernel(const float* __restrict__ k)
{
    extern __shared__ char sm[];
    const uint32_t sb = u32p(sm);
    float* pews = (float*)(sm + G0_PEW);
    const int mt = blockIdx.x, bh = blockIdx.y;
    const int tid = threadIdx.x, lane = tid & 31, wid = tid >> 5;
    const int rt = wid & 3, cg = wid >> 2;
    const float* Abase = k + (size_t)bh * S_LEN * 128 + (size_t)mt * 64 * 256;

    float acc[8][4];
#pragma unroll
    for (int t = 0; t < 8; t++)
#pragma unroll
        for (int j = 0; j < 4; j++) acc[t][j] = 0.f;

#pragma unroll
    for (int i = 0; i < 2; ++i)
        ((float4*)pews)[tid + i * 256] = ((const float4*)g_pew)[tid + i * 256];

    // prologue: A0 (LDG/split/STS) + B0 (cp.async)
    {
        float4 rA[4];
#pragma unroll
        for (int t = 0; t < 4; ++t) {
            int f = tid + t * 256, row = f >> 4, fc = f & 15;
            rA[t] = *(const float4*)(Abase + (size_t)row * 256 + 4 * fc);
        }
        prefB(sb + 32768, g_w_hi, g_w_lo, 256, 0, tid);
        cpcommit();
        g0_sts_A(sm, 0, rA, tid);
    }
    cpwait0(); __syncthreads();

    for (int c = 0; c < 4; ++c) {
        float4 rA[4];
        if (c < 3) {
#pragma unroll
            for (int t = 0; t < 4; ++t) {
                int f = tid + t * 256, row = f >> 4, fc = f & 15;
                rA[t] = *(const float4*)(Abase + (size_t)row * 256 + (c + 1) * 64 + 4 * fc);
            }
            prefB(sb + 32768 + ((c + 1) & 1) * 32768, g_w_hi, g_w_lo, 256,
                  (c + 1) * 64, tid);
            cpcommit();
        }
        const uint32_t aU = sb + (c & 1) * 16384;
        const uint32_t bU = sb + 32768 + (c & 1) * 32768;
        mma_r1t8(acc, aU, aU + 8192, bU, bU + 16384, rt, cg, lane);
        if (c < 3) {
            g0_sts_A(sm, ((c + 1) & 1) * 16384, rA, tid);
            cpwait0();
        }
        __syncthreads();
    }

    // epilogue: pair j feeds two act0 rows (different pe bias)
    const int r0 = lane >> 2, cof = (lane & 3) << 1;
    const size_t bhbase = (size_t)bh * NWIN;
#pragma unroll
    for (int t = 0; t < 8; t++) {
        int col = (cg * 8 + t) * 8 + cof;
        float* cc = acc[t];
#pragma unroll
        for (int h = 0; h < 2; h++) {
            int r = rt * 16 + r0 + (h << 3);
            int j = mt * 64 + r;
            float y0 = cc[2*h], y1 = cc[2*h + 1];
            int w1 = j >> 3, ra = j & 7;
            if (w1 < NWIN) {
                float2 bb = *(const float2*)(pews + ra * 128 + col);
                silu_split_store(g_a0_hi, g_a0_lo,
                    ((bhbase + w1) * 16 + ra) * 128 + col, y0 + bb.x, y1 + bb.y);
            }
            if (w1 >= 1) {
                int rb = ra + 8;
                float2 bb = *(const float2*)(pews + rb * 128 + col);
                silu_split_store(g_a0_hi, g_a0_lo,
                    ((bhbase + (w1 - 1)) * 16 + rb) * 128 + col, y0 + bb.x, y1 + bb.y);
            }
        }
    }
}

// ===========================================================================
// G1..G3: 256-thread CTAs, M-tile=64, 96KB smem -> 2 CTAs/SM (proven r10)
// ===========================================================================
#define GS_SMEM 98304

template<int STAGE>
__global__ void __launch_bounds__(256, 2)
gstage_kernel()
{
    const __nv_bfloat16 *aHi, *aLo, *wh, *wl;
    __nv_bfloat16 *oHi, *oLo;
    int Mtot;
    if constexpr (STAGE == 1) { aHi=g_a0_hi; aLo=g_a0_lo; wh=g_w_hi+32768; wl=g_w_lo+32768; oHi=g_a1_hi; oLo=g_a1_lo; Mtot=M1; }
    if constexpr (STAGE == 2) { aHi=g_a1_hi; aLo=g_a1_lo; wh=g_w_hi+65536; wl=g_w_lo+65536; oHi=g_a2_hi; oLo=g_a2_lo; Mtot=M2; }
    if constexpr (STAGE == 3) { aHi=g_a2_hi; aLo=g_a2_lo; wh=g_w_hi+98304; wl=g_w_lo+98304; oHi=g_a3_hi; oLo=g_a3_lo; Mtot=M3; }

    extern __shared__ char sm[];
    const uint32_t sb = u32p(sm);
    const int mt = blockIdx.x;
    const int tid = threadIdx.x, lane = tid & 31, wid = tid >> 5;
    const int rt = wid & 3, cg = wid >> 2;

    float acc[8][4];
#pragma unroll
    for (int t = 0; t < 8; t++)
#pragma unroll
        for (int j = 0; j < 4; j++) acc[t][j] = 0.f;

    prefA64(sb, aHi, aLo, 256, Mtot, mt, 0, tid);
    prefB(sb + 32768, wh, wl, 256, 0, tid);
    cpcommit();

    for (int c = 0; c < 4; ++c) {
        cpwait0();
        __syncthreads();
        if (c + 1 < 4) {
            int b = (c + 1) & 1;
            prefA64(sb + b * 16384, aHi, aLo, 256, Mtot, mt, (c + 1) * 64, tid);
            prefB(sb + 32768 + b * 32768, wh, wl, 256, (c + 1) * 64, tid);
            cpcommit();
        }
        const uint32_t aU = sb + (c & 1) * 16384;
        const uint32_t bU = sb + 32768 + (c & 1) * 32768;
        mma_r1t8(acc, aU, aU + 8192, bU, bU + 16384, rt, cg, lane);
    }

    const int r0 = lane >> 2, cof = (lane & 3) << 1;
#pragma unroll
    for (int t = 0; t < 8; t++) {
        int col = (cg * 8 + t) * 8 + cof;
        float* cc = acc[t];
#pragma unroll
        for (int h = 0; h < 2; h++) {
            int r = rt * 16 + r0 + (h << 3);
            int m = mt * 64 + r;
            if (m < Mtot)
                silu_split_store(oHi, oLo, (size_t)m * 128 + col,
                                 cc[2*h], cc[2*h + 1]);
        }
    }
}

// ===========================================================================
// G45: stage 4 (K=256 from a3) + stage 5 (K=128, w_stop) fused; 2 CTAs/SM.
// Stage-5 A = silu(stage-4 acc) split directly into the smem A buffers.
// ===========================================================================
__global__ void __launch_bounds__(256, 2)
g45_kernel(float* __restrict__ gout)
{
    extern __shared__ char sm[];
    const uint32_t sb = u32p(sm);
    const int mt = blockIdx.x;
    const int tid = threadIdx.x, lane = tid & 31, wid = tid >> 5;
    const int rt = wid & 3, cg = wid >> 2;
    const int r0 = lane >> 2, cof = (lane & 3) << 1;

    float acc[8][4];
#pragma unroll
    for (int t = 0; t < 8; t++)
#pragma unroll
        for (int j = 0; j < 4; j++) acc[t][j] = 0.f;

    // ---- stage 4 ----
    prefA64(sb, g_a3_hi, g_a3_lo, 256, M4, mt, 0, tid);
    prefB(sb + 32768, g_w_hi + 131072, g_w_lo + 131072, 256, 0, tid);
    cpcommit();
    for (int c = 0; c < 4; ++c) {
        cpwait0();
        __syncthreads();
        if (c + 1 < 4) {
            int b = (c + 1) & 1;
            prefA64(sb + b * 16384, g_a3_hi, g_a3_lo, 256, M4, mt, (c + 1) * 64, tid);
            prefB(sb + 32768 + b * 32768, g_w_hi + 131072, g_w_lo + 131072,
                  256, (c + 1) * 64, tid);
            cpcommit();
        }
        const uint32_t aU = sb + (c & 1) * 16384;
        const uint32_t bU = sb + 32768 + (c & 1) * 32768;
        mma_r1t8(acc, aU, aU + 8192, bU, bU + 16384, rt, cg, lane);
    }
    __syncthreads();   // all reads of A/B buffers done

    // ---- stage-5 staging: w_stop chunks into B0,B1; A = silu(acc4) -> A bufs
    prefB(sb + 32768, g_w_hi + 163840, g_w_lo + 163840, 128, 0, tid);
    prefB(sb + 65536, g_w_hi + 163840, g_w_lo + 163840, 128, 64, tid);
    cpcommit();
#pragma unroll
    for (int t = 0; t < 8; t++) {
        int col = (cg * 8 + t) * 8 + cof;
        float* cc = acc[t];
#pragma unroll
        for (int h = 0; h < 2; h++) {
            int r = rt * 16 + r0 + (h << 3);
            float v0 = silu_f(cc[2*h]), v1 = silu_f(cc[2*h + 1]);
            U2b hi, lo;
            hi.b[0] = __float2bfloat16(v0);
            hi.b[1] = __float2bfloat16(v1);
            lo.b[0] = __float2bfloat16(v0 - __bfloat162float(hi.b[0]));
            lo.b[1] = __float2bfloat16(v1 - __bfloat162float(hi.b[1]));
            int b = col >> 6, lc = col & 63, g = lc >> 3;
            int off = b * 16384 + r * 128 + ((g ^ (r & 7)) << 4) + (lc & 7) * 2;
            *(uint32_t*)(sm + off)        = hi.u;
            *(uint32_t*)(sm + off + 8192) = lo.u;
        }
    }
    cpwait0();
    __syncthreads();

    // ---- stage 5: 2 resident chunks ----
    float acc5[8][4];
#pragma unroll
    for (int t = 0; t < 8; t++)
#pragma unroll
        for (int j = 0; j < 4; j++) acc5[t][j] = 0.f;
#pragma unroll
    for (int c = 0; c < 2; ++c) {
        const uint32_t aU = sb + c * 16384;
        const uint32_t bU = sb + 32768 + c * 32768;
        mma_r1t8(acc5, aU, aU + 8192, bU, bU + 16384, rt, cg, lane);
    }

    // ---- final epilogue -> gmem ----
#pragma unroll
    for (int t = 0; t < 8; t++) {
        int col = (cg * 8 + t) * 8 + cof;
        float* cc = acc5[t];
#pragma unroll
        for (int h = 0; h < 2; h++) {
            int r = rt * 16 + r0 + (h << 3);
            int m = mt * 64 + r;
            if (m < M4) {
                int bh = m / NWIN, w = m % NWIN;
                *(float2*)(gout + ((size_t)bh * 512 + 1 + w) * 128 + col) =
                    make_float2(cc[2*h], cc[2*h + 1]);
            }
        }
    }
}

extern "C" void kernel_launch(void* const* d_in, const int* in_sizes, int n_in,
                              void* d_out, int out_size)
{
    const float* k  = (const float*)d_in[0];
    const float* pe = (const float*)d_in[1];
    const float* wd = (const float*)d_in[2];
    const float* ws = (const float*)d_in[3];
    float* out = (float*)d_out;

    split_weights_kernel<<<(WTOT + 255) / 256, 256>>>(wd, ws);
    prep_pew_kernel<<<8, 256>>>(wd, pe);
    zero_out_kernel<<<16, 256>>>(out);

    cudaFuncSetAttribute(g0_kernel,
                         cudaFuncAttributeMaxDynamicSharedMemorySize, G0_SMEM);
    cudaFuncSetAttribute(gstage_kernel<1>,
                         cudaFuncAttributeMaxDynamicSharedMemorySize, GS_SMEM);
    cudaFuncSetAttribute(gstage_kernel<2>,
                         cudaFuncAttributeMaxDynamicSharedMemorySize, GS_SMEM);
    cudaFuncSetAttribute(gstage_kernel<3>,
                         cudaFuncAttributeMaxDynamicSharedMemorySize, GS_SMEM);
    cudaFuncSetAttribute(g45_kernel,
                         cudaFuncAttributeMaxDynamicSharedMemorySize, GS_SMEM);

    g0_kernel<<<dim3(64, BH), 256, G0_SMEM>>>(k);                 // 2048 CTAs
    gstage_kernel<1><<<(M1 + 63) / 64, 256, GS_SMEM>>>();         // 2044
    gstage_kernel<2><<<(M2 + 63) / 64, 256, GS_SMEM>>>();         // 1022
    gstage_kernel<3><<<(M3 + 63) / 64, 256, GS_SMEM>>>();         // 511
    g45_kernel<<<(M4 + 63) / 64, 256, GS_SMEM>>>(out);            // 256
}

// round 12
// speedup vs baseline: 1.0400x; 1.0400x over previous
#include <cuda_runtime.h>
#include <cuda_bf16.h>
#include <cstdint>

#define S_LEN  8192
#define BH     32
#define NWIN   511
#define WTOT   (5*128*256 + 128*128)

#define M1 (BH*NWIN*8)   // 130816
#define M2 (BH*NWIN*4)   // 65408
#define M3 (BH*NWIN*2)   // 32704
#define M4 (BH*NWIN)     // 16352

__device__ __nv_bfloat16 g_w_hi[WTOT];
__device__ __nv_bfloat16 g_w_lo[WTOT];
__device__ float         g_pew[16 * 128];
__device__ __nv_bfloat16 g_a0_hi[(size_t)BH*NWIN*16*128], g_a0_lo[(size_t)BH*NWIN*16*128];
__device__ __nv_bfloat16 g_a1_hi[(size_t)M1*128],         g_a1_lo[(size_t)M1*128];
__device__ __nv_bfloat16 g_a2_hi[(size_t)M2*128],         g_a2_lo[(size_t)M2*128];
__device__ __nv_bfloat16 g_a3_hi[(size_t)M3*128],         g_a3_lo[(size_t)M3*128];

union U8b { __nv_bfloat16 b[8]; uint4 v; };
union U4b { __nv_bfloat16 b[4]; unsigned long long u; };
union U2b { __nv_bfloat16 b[2]; uint32_t u; };

// ---------------------------------------------------------------------------
__global__ void split_weights_kernel(const float* __restrict__ wd,
                                     const float* __restrict__ ws) {
    int i = blockIdx.x * blockDim.x + threadIdx.x;
    if (i >= WTOT) return;
    float v = (i < 5*128*256) ? wd[i] : ws[i - 5*128*256];
    __nv_bfloat16 h = __float2bfloat16(v);
    g_w_hi[i] = h;
    g_w_lo[i] = __float2bfloat16(v - __bfloat162float(h));
}

__global__ void prep_pew_kernel(const float* __restrict__ wd,
                                const float* __restrict__ pe) {
    int idx = blockIdx.x * blockDim.x + threadIdx.x;   // 2048
    int j = idx >> 7, n = idx & 127;
    float s = 0.f;
    for (int d = 0; d < 128; ++d) {
        s += pe[(2*j)*128 + d]   * wd[n*256 + d];
        s += pe[(2*j+1)*128 + d] * wd[n*256 + 128 + d];
    }
    g_pew[idx] = s;
}

__global__ void zero_out_kernel(float* __restrict__ out) {
    int i = blockIdx.x * 256 + threadIdx.x;
    if (i < 4096)
        out[(size_t)(i >> 7) * 512 * 128 + (i & 127)] = 0.f;
}

// ---------------------------------------------------------------------------
__device__ __forceinline__ uint32_t u32p(const void* p) {
    return (uint32_t)__cvta_generic_to_shared(p);
}
__device__ __forceinline__ void ldmx4(uint32_t* r, uint32_t addr) {
    asm volatile("ldmatrix.sync.aligned.m8n8.x4.shared.b16 {%0,%1,%2,%3}, [%4];"
                 : "=r"(r[0]), "=r"(r[1]), "=r"(r[2]), "=r"(r[3]) : "r"(addr));
}
__device__ __forceinline__ void mma16816(float* c, const uint32_t* a,
                                         uint32_t b0, uint32_t b1) {
    asm volatile("mma.sync.aligned.m16n8k16.row.col.f32.bf16.bf16.f32 "
                 "{%0,%1,%2,%3}, {%4,%5,%6,%7}, {%8,%9}, {%0,%1,%2,%3};"
                 : "+f"(c[0]), "+f"(c[1]), "+f"(c[2]), "+f"(c[3])
                 : "r"(a[0]), "r"(a[1]), "r"(a[2]), "r"(a[3]), "r"(b0), "r"(b1));
}
__device__ __forceinline__ float silu_f(float x) { return x / (1.f + __expf(-x)); }

__device__ __forceinline__ void cpasync16(uint32_t dst, const void* src) {
    asm volatile("cp.async.cg.shared.global [%0], [%1], 16;" :: "r"(dst), "l"(src));
}
__device__ __forceinline__ void cpasync16z(uint32_t dst, const void* src, bool v) {
    int sz = v ? 16 : 0;
    asm volatile("cp.async.cg.shared.global [%0], [%1], 16, %2;"
                 :: "r"(dst), "l"(src), "r"(sz));
}
__device__ __forceinline__ void cpcommit() {
    asm volatile("cp.async.commit_group;" ::: "memory");
}
__device__ __forceinline__ void cpwait0() { asm volatile("cp.async.wait_group 0;" ::: "memory"); }

// silu + split 8 fp32 -> coalesced 16B hi/lo stores
__device__ __forceinline__ void silu_split8_store(
        __nv_bfloat16* hiA, __nv_bfloat16* loA, size_t idx, const float* y) {
    U8b hi, lo;
#pragma unroll
    for (int j = 0; j < 8; j++) {
        float s = silu_f(y[j]);
        hi.b[j] = __float2bfloat16(s);
        lo.b[j] = __float2bfloat16(s - __bfloat162float(hi.b[j]));
    }
    *(uint4*)(hiA + idx) = hi.v;
    *(uint4*)(loA + idx) = lo.v;
}

// B chunk [128 n x 64 k] hi+lo -> swizzled smem
template<int NT>
__device__ __forceinline__ void prefB(uint32_t bufU,
        const __nv_bfloat16* __restrict__ wh, const __nv_bfloat16* __restrict__ wl,
        int KDIM, int kb, int tid) {
#pragma unroll
    for (int it = 0; it < 2048 / NT; ++it) {
        int i = tid + it * NT;
        int g = i & 7, n = (i >> 3) & 127, hl = i >> 10;
        const __nv_bfloat16* src = (hl ? wl : wh) + n * KDIM + kb + g * 8;
        uint32_t dst = bufU + hl * 16384 + n * 128 + ((g ^ (n & 7)) << 4);
        cpasync16(dst, src);
    }
}

// A chunk [64 rows x 64 k] hi+lo from pre-split act arrays (256 threads)
__device__ __forceinline__ void prefA64(uint32_t bufU,
        const __nv_bfloat16* __restrict__ aHi, const __nv_bfloat16* __restrict__ aLo,
        int KD, int Mtot, int mt, int kb, int tid) {
#pragma unroll
    for (int it = 0; it < 4; ++it) {
        int i = tid + it * 256;
        int g = i & 7, row = (i >> 3) & 63, hl = i >> 9;
        int mrow = mt * 64 + row;
        bool v = mrow < Mtot;
        const __nv_bfloat16* src = (hl ? aLo : aHi)
                                 + (size_t)(v ? mrow : 0) * KD + kb + g * 8;
        uint32_t dst = bufU + hl * 8192 + row * 128 + ((g ^ (row & 7)) << 4);
        cpasync16z(dst, src, v);
    }
}

// R=2 x T=4 warp tile over one 64-col chunk (16 warps: 4 row x 4 colgroup)
__device__ __forceinline__ void mma_chunk64(
    float (&acc)[2][4][4],
    uint32_t aHiU, uint32_t aLoU, uint32_t bHiU, uint32_t bLoU,
    int rBeg, int ntBeg, int lane)
{
    const int a_mat    = lane >> 3;
    const int a_rowoff = (lane & 7) + ((a_mat & 1) << 3);
    const int a_koff   = (a_mat >> 1) << 3;
    const int b_nl     = lane & 7;
    const int b_km     = (lane >> 3) << 3;
#pragma unroll
    for (int kq = 0; kq < 64; kq += 32) {
        uint32_t aH[2][8], aL[2][8];
#pragma unroll
        for (int i = 0; i < 2; i++) {
            int Rr = (rBeg + i) * 16 + a_rowoff;
            int kc0 = kq + a_koff;
            int offs0 = Rr * 128 + (((kc0 >> 3) ^ (Rr & 7)) << 4);
            int offs1 = Rr * 128 + ((((kc0 + 16) >> 3) ^ (Rr & 7)) << 4);
            ldmx4(aH[i], aHiU + offs0);
            ldmx4(aH[i] + 4, aHiU + offs1);
            ldmx4(aL[i], aLoU + offs0);
            ldmx4(aL[i] + 4, aLoU + offs1);
        }
#pragma unroll
        for (int t = 0; t < 4; t++) {
            int n = ((ntBeg + t) << 3) + b_nl;
            int cs = ((kq + b_km) >> 3) ^ (n & 7);
            uint32_t boff = n * 128 + (cs << 4);
            uint32_t bH[4], bL[4];
            ldmx4(bH, bHiU + boff);
            ldmx4(bL, bLoU + boff);
#pragma unroll
            for (int i = 0; i < 2; i++) {
                float* cc = acc[i][t];
                mma16816(cc, aH[i], bH[0], bH[1]);
                mma16816(cc, aL[i], bH[0], bH[1]);
                mma16816(cc, aH[i], bL[0], bL[1]);
                mma16816(cc, aH[i] + 4, bH[2], bH[3]);
                mma16816(cc, aL[i] + 4, bH[2], bH[3]);
                mma16816(cc, aH[i] + 4, bL[2], bL[3]);
            }
        }
    }
}

// R=1 x T=8 warp tile (8 warps: 4 row x 2 colgroup)
__device__ __forceinline__ void mma_r1t8(
    float (&acc)[8][4],
    uint32_t aHiU, uint32_t aLoU, uint32_t bHiU, uint32_t bLoU,
    int rt, int cg, int lane)
{
    const int a_rowoff = (lane & 7) + (((lane >> 3) & 1) << 3);
    const int a_koff   = (lane >> 4) << 3;
    const int b_nl     = lane & 7;
    const int b_koff   = ((lane >> 3) & 1) << 3;
    const int b_nts    = lane >> 4;
#pragma unroll
    for (int kq = 0; kq < 64; kq += 16) {
        int Rr = rt * 16 + a_rowoff;
        int kc = kq + a_koff;
        int offs = Rr * 128 + (((kc >> 3) ^ (Rr & 7)) << 4);
        uint32_t aH[4], aL[4];
        ldmx4(aH, aHiU + offs);
        ldmx4(aL, aLoU + offs);
#pragma unroll
        for (int tp = 0; tp < 4; tp++) {
            int n = (cg * 8 + tp * 2 + b_nts) * 8 + b_nl;
            int cs = ((kq + b_koff) >> 3) ^ (n & 7);
            uint32_t boff = (uint32_t)(n * 128 + (cs << 4));
            uint32_t bH[4], bL[4];
            ldmx4(bH, bHiU + boff);
            ldmx4(bL, bLoU + boff);
#pragma unroll
            for (int sub = 0; sub < 2; sub++) {
                float* cc = acc[tp * 2 + sub];
                mma16816(cc, aH, bH[2*sub], bH[2*sub+1]);
                mma16816(cc, aL, bH[2*sub], bH[2*sub+1]);
                mma16816(cc, aH, bL[2*sub], bL[2*sub+1]);
            }
        }
    }
}

// ===========================================================================
// G0 (r10 proven mainloop, 512 threads, 128-pair tiles) + transpose epilogue.
// smem: A0 @0 (hi/lo 16384), A1 @32768; B @65536,98304; pew @131072.
// Epilogue ybuf: fp32 [128][132] @0 (67584 B, all free after final sync).
// ===========================================================================
#define G0_OFFB(b) (65536 + (b)*32768)
#define G0_PEW     131072
#define G0_SMEM    (131072 + 8192)

__device__ __forceinline__ void g0_sts_A(char* sm, int bufByte, const float4* rA,
                                         int tid) {
#pragma unroll
    for (int t = 0; t < 4; ++t) {
        int f = tid + t * 512, row = f >> 4, fc = f & 15;
        float v[4] = {rA[t].x, rA[t].y, rA[t].z, rA[t].w};
        U4b hi, lo;
#pragma unroll
        for (int j = 0; j < 4; j++) {
            hi.b[j] = __float2bfloat16(v[j]);
            lo.b[j] = __float2bfloat16(v[j] - __bfloat162float(hi.b[j]));
        }
        int g = fc >> 1;
        int off = bufByte + row * 128 + ((g ^ (row & 7)) << 4) + (fc & 1) * 8;
        *(unsigned long long*)(sm + off)         = hi.u;
        *(unsigned long long*)(sm + off + 16384) = lo.u;
    }
}

__global__ void __launch_bounds__(512, 1)
g0_kernel(const float* __restrict__ k)
{
    extern __shared__ char sm[];
    const uint32_t sb = u32p(sm);
    float* pews = (float*)(sm + G0_PEW);
    const int mt = blockIdx.x, bh = blockIdx.y;
    const int tid = threadIdx.x, lane = tid & 31, wid = tid >> 5;
    const int rBeg = (wid & 3) * 2;
    const int cg   = wid >> 2;
    const float* Abase = k + (size_t)bh * S_LEN * 128 + (size_t)mt * 128 * 256;

    float acc[2][4][4];
#pragma unroll
    for (int i = 0; i < 2; i++)
#pragma unroll
        for (int t = 0; t < 4; t++)
#pragma unroll
            for (int j = 0; j < 4; j++) acc[i][t][j] = 0.f;

    ((float4*)pews)[tid] = ((const float4*)g_pew)[tid];

    // prologue: A0 (LDG/split/STS) + B0 (cp.async)
    {
        float4 rA[4];
#pragma unroll
        for (int t = 0; t < 4; ++t) {
            int f = tid + t * 512, row = f >> 4, fc = f & 15;
            rA[t] = *(const float4*)(Abase + (size_t)row * 256 + 4 * fc);
        }
        prefB<512>(sb + G0_OFFB(0), g_w_hi, g_w_lo, 256, 0, tid);
        cpcommit();
        g0_sts_A(sm, 0, rA, tid);
    }
    cpwait0(); __syncthreads();

    for (int c = 0; c < 4; ++c) {
        float4 rA[4];
        if (c < 3) {
#pragma unroll
            for (int t = 0; t < 4; ++t) {
                int f = tid + t * 512, row = f >> 4, fc = f & 15;
                rA[t] = *(const float4*)(Abase + (size_t)row * 256 + (c + 1) * 64 + 4 * fc);
            }
            prefB<512>(sb + G0_OFFB((c + 1) & 1), g_w_hi, g_w_lo, 256, (c + 1) * 64, tid);
            cpcommit();
        }
        const uint32_t aU = sb + (c & 1) * 32768;
        const uint32_t bU = sb + G0_OFFB(c & 1);
        mma_chunk64(acc, aU, aU + 16384, bU, bU + 16384, rBeg, cg * 4, lane);
        if (c < 3) {
            g0_sts_A(sm, ((c + 1) & 1) * 32768, rA, tid);
            cpwait0();
        }
        __syncthreads();
    }

    // ---- transpose epilogue ----
    float* ybuf = (float*)sm;     // [128][132] fp32
    const int r0 = lane >> 2, cof = (lane & 3) << 1;
#pragma unroll
    for (int i = 0; i < 2; i++)
#pragma unroll
        for (int t = 0; t < 4; t++) {
            int col = (cg * 4 + t) * 8 + cof;
            float* cc = acc[i][t];
#pragma unroll
            for (int h = 0; h < 2; h++) {
                int r = (rBeg + i) * 16 + r0 + (h << 3);
                *(float2*)(ybuf + r * 132 + col) = make_float2(cc[2*h], cc[2*h+1]);
            }
        }
    __syncthreads();

    const size_t bhbase = (size_t)bh * NWIN;
#pragma unroll
    for (int it = 0; it < 4; ++it) {
        int idx = tid + it * 512;            // 2048 units: 128 rows x 16 blocks
        int row = idx >> 4, cb = (idx & 15) << 3;
        float4 va = *(const float4*)(ybuf + row * 132 + cb);
        float4 vb = *(const float4*)(ybuf + row * 132 + cb + 4);
        float y[8] = {va.x, va.y, va.z, va.w, vb.x, vb.y, vb.z, vb.w};
        int j = mt * 128 + row;
        int w1 = j >> 3, ra = j & 7;
        if (w1 < NWIN) {
            const float* bp = pews + ra * 128 + cb;
            float z[8];
#pragma unroll
            for (int q = 0; q < 8; q++) z[q] = y[q] + bp[q];
            silu_split8_store(g_a0_hi, g_a0_lo,
                ((bhbase + w1) * 16 + ra) * 128 + cb, z);
        }
        if (w1 >= 1) {
            const float* bp = pews + (8 + ra) * 128 + cb;
            float z[8];
#pragma unroll
            for (int q = 0; q < 8; q++) z[q] = y[q] + bp[q];
            silu_split8_store(g_a0_hi, g_a0_lo,
                ((bhbase + (w1 - 1)) * 16 + 8 + ra) * 128 + cb, z);
        }
    }
}

// ===========================================================================
// G1..G3: 256-thread CTAs, M-tile=64, 96KB -> 2 CTAs/SM, transpose epilogue.
// ===========================================================================
#define GS_SMEM 98304

template<int STAGE>
__global__ void __launch_bounds__(256, 2)
gstage_kernel()
{
    const __nv_bfloat16 *aHi, *aLo, *wh, *wl;
    __nv_bfloat16 *oHi, *oLo;
    int Mtot;
    if constexpr (STAGE == 1) { aHi=g_a0_hi; aLo=g_a0_lo; wh=g_w_hi+32768; wl=g_w_lo+32768; oHi=g_a1_hi; oLo=g_a1_lo; Mtot=M1; }
    if constexpr (STAGE == 2) { aHi=g_a1_hi; aLo=g_a1_lo; wh=g_w_hi+65536; wl=g_w_lo+65536; oHi=g_a2_hi; oLo=g_a2_lo; Mtot=M2; }
    if constexpr (STAGE == 3) { aHi=g_a2_hi; aLo=g_a2_lo; wh=g_w_hi+98304; wl=g_w_lo+98304; oHi=g_a3_hi; oLo=g_a3_lo; Mtot=M3; }

    extern __shared__ char sm[];
    const uint32_t sb = u32p(sm);
    const int mt = blockIdx.x;
    const int tid = threadIdx.x, lane = tid & 31, wid = tid >> 5;
    const int rt = wid & 3, cg = wid >> 2;

    float acc[8][4];
#pragma unroll
    for (int t = 0; t < 8; t++)
#pragma unroll
        for (int j = 0; j < 4; j++) acc[t][j] = 0.f;

    prefA64(sb, aHi, aLo, 256, Mtot, mt, 0, tid);
    prefB<256>(sb + 32768, wh, wl, 256, 0, tid);
    cpcommit();

    for (int c = 0; c < 4; ++c) {
        cpwait0();
        __syncthreads();
        if (c + 1 < 4) {
            int b = (c + 1) & 1;
            prefA64(sb + b * 16384, aHi, aLo, 256, Mtot, mt, (c + 1) * 64, tid);
            prefB<256>(sb + 32768 + b * 32768, wh, wl, 256, (c + 1) * 64, tid);
            cpcommit();
        }
        const uint32_t aU = sb + (c & 1) * 16384;
        const uint32_t bU = sb + 32768 + (c & 1) * 32768;
        mma_r1t8(acc, aU, aU + 8192, bU, bU + 16384, rt, cg, lane);
    }
    __syncthreads();   // all reads done; smem free

    // ---- transpose epilogue ----
    float* ybuf = (float*)sm;     // [64][132] fp32 (33792 B)
    const int r0 = lane >> 2, cof = (lane & 3) << 1;
#pragma unroll
    for (int t = 0; t < 8; t++) {
        int col = (cg * 8 + t) * 8 + cof;
        float* cc = acc[t];
#pragma unroll
        for (int h = 0; h < 2; h++) {
            int r = rt * 16 + r0 + (h << 3);
            *(float2*)(ybuf + r * 132 + col) = make_float2(cc[2*h], cc[2*h+1]);
        }
    }
    __syncthreads();

#pragma unroll
    for (int it = 0; it < 4; ++it) {
        int idx = tid + it * 256;            // 1024 units: 64 rows x 16 blocks
        int row = idx >> 4, cb = (idx & 15) << 3;
        int m = mt * 64 + row;
        if (m < Mtot) {
            float4 va = *(const float4*)(ybuf + row * 132 + cb);
            float4 vb = *(const float4*)(ybuf + row * 132 + cb + 4);
            float y[8] = {va.x, va.y, va.z, va.w, vb.x, vb.y, vb.z, vb.w};
            silu_split8_store(oHi, oLo, (size_t)m * 128 + cb, y);
        }
    }
}

// ===========================================================================
// G45: stage 4 (K=256 from a3) + stage 5 (K=128, w_stop) fused; 2 CTAs/SM.
// ===========================================================================
__global__ void __launch_bounds__(256, 2)
g45_kernel(float* __restrict__ gout)
{
    extern __shared__ char sm[];
    const uint32_t sb = u32p(sm);
    const int mt = blockIdx.x;
    const int tid = threadIdx.x, lane = tid & 31, wid = tid >> 5;
    const int rt = wid & 3, cg = wid >> 2;
    const int r0 = lane >> 2, cof = (lane & 3) << 1;

    float acc[8][4];
#pragma unroll
    for (int t = 0; t < 8; t++)
#pragma unroll
        for (int j = 0; j < 4; j++) acc[t][j] = 0.f;

    // ---- stage 4 ----
    prefA64(sb, g_a3_hi, g_a3_lo, 256, M4, mt, 0, tid);
    prefB<256>(sb + 32768, g_w_hi + 131072, g_w_lo + 131072, 256, 0, tid);
    cpcommit();
    for (int c = 0; c < 4; ++c) {
        cpwait0();
        __syncthreads();
        if (c + 1 < 4) {
            int b = (c + 1) & 1;
            prefA64(sb + b * 16384, g_a3_hi, g_a3_lo, 256, M4, mt, (c + 1) * 64, tid);
            prefB<256>(sb + 32768 + b * 32768, g_w_hi + 131072, g_w_lo + 131072,
                       256, (c + 1) * 64, tid);
            cpcommit();
        }
        const uint32_t aU = sb + (c & 1) * 16384;
        const uint32_t bU = sb + 32768 + (c & 1) * 32768;
        mma_r1t8(acc, aU, aU + 8192, bU, bU + 16384, rt, cg, lane);
    }
    __syncthreads();

    // ---- stage-5 staging ----
    prefB<256>(sb + 32768, g_w_hi + 163840, g_w_lo + 163840, 128, 0, tid);
    prefB<256>(sb + 65536, g_w_hi + 163840, g_w_lo + 163840, 128, 64, tid);
    cpcommit();
#pragma unroll
    for (int t = 0; t < 8; t++) {
        int col = (cg * 8 + t) * 8 + cof;
        float* cc = acc[t];
#pragma unroll
        for (int h = 0; h < 2; h++) {
            int r = rt * 16 + r0 + (h << 3);
            float v0 = silu_f(cc[2*h]), v1 = silu_f(cc[2*h + 1]);
            U2b hi, lo;
            hi.b[0] = __float2bfloat16(v0);
            hi.b[1] = __float2bfloat16(v1);
            lo.b[0] = __float2bfloat16(v0 - __bfloat162float(hi.b[0]));
            lo.b[1] = __float2bfloat16(v1 - __bfloat162float(hi.b[1]));
            int b = col >> 6, lc = col & 63, g = lc >> 3;
            int off = b * 16384 + r * 128 + ((g ^ (r & 7)) << 4) + (lc & 7) * 2;
            *(uint32_t*)(sm + off)        = hi.u;
            *(uint32_t*)(sm + off + 8192) = lo.u;
        }
    }
    cpwait0();
    __syncthreads();

    // ---- stage 5 ----
    float acc5[8][4];
#pragma unroll
    for (int t = 0; t < 8; t++)
#pragma unroll
        for (int j = 0; j < 4; j++) acc5[t][j] = 0.f;
#pragma unroll
    for (int c = 0; c < 2; ++c) {
        const uint32_t aU = sb + c * 16384;
        const uint32_t bU = sb + 32768 + c * 32768;
        mma_r1t8(acc5, aU, aU + 8192, bU, bU + 16384, rt, cg, lane);
    }

    // final fp32 store (float2: 32B/quad contiguous, full sectors)
#pragma unroll
    for (int t = 0; t < 8; t++) {
        int col = (cg * 8 + t) * 8 + cof;
        float* cc = acc5[t];
#pragma unroll
        for (int h = 0; h < 2; h++) {
            int r = rt * 16 + r0 + (h << 3);
            int m = mt * 64 + r;
            if (m < M4) {
                int bh = m / NWIN, w = m % NWIN;
                *(float2*)(gout + ((size_t)bh * 512 + 1 + w) * 128 + col) =
                    make_float2(cc[2*h], cc[2*h + 1]);
            }
        }
    }
}

extern "C" void kernel_launch(void* const* d_in, const int* in_sizes, int n_in,
                              void* d_out, int out_size)
{
    const float* k  = (const float*)d_in[0];
    const float* pe = (const float*)d_in[1];
    const float* wd = (const float*)d_in[2];
    const float* ws = (const float*)d_in[3];
    float* out = (float*)d_out;

    split_weights_kernel<<<(WTOT + 255) / 256, 256>>>(wd, ws);
    prep_pew_kernel<<<8, 256>>>(wd, pe);
    zero_out_kernel<<<16, 256>>>(out);

    cudaFuncSetAttribute(g0_kernel,
                         cudaFuncAttributeMaxDynamicSharedMemorySize, G0_SMEM);
    cudaFuncSetAttribute(gstage_kernel<1>,
                         cudaFuncAttributeMaxDynamicSharedMemorySize, GS_SMEM);
    cudaFuncSetAttribute(gstage_kernel<2>,
                         cudaFuncAttributeMaxDynamicSharedMemorySize, GS_SMEM);
    cudaFuncSetAttribute(gstage_kernel<3>,
                         cudaFuncAttributeMaxDynamicSharedMemorySize, GS_SMEM);
    cudaFuncSetAttribute(g45_kernel,
                         cudaFuncAttributeMaxDynamicSharedMemorySize, GS_SMEM);

    g0_kernel<<<dim3(32, BH), 512, G0_SMEM>>>(k);                 // 1024 CTAs
    gstage_kernel<1><<<(M1 + 63) / 64, 256, GS_SMEM>>>();         // 2044
    gstage_kernel<2><<<(M2 + 63) / 64, 256, GS_SMEM>>>();         // 1022
    gstage_kernel<3><<<(M3 + 63) / 64, 256, GS_SMEM>>>();         // 511
    g45_kernel<<<(M4 + 63) / 64, 256, GS_SMEM>>>(out);            // 256
}